// round 2
// baseline (speedup 1.0000x reference)
#include <cuda_runtime.h>
#include <math.h>

#define SEQLEN   2048
#define DIM      4096
#define NHEADS   32
#define NKV      8
#define HD       128
#define WINDOW   4096
#define QSTRIDE  (NHEADS * HD)   // 4096
#define KSTRIDE  (NKV * HD)      // 1024
#define ATT_SCALE 0.08838834764831843f  // 128^-0.5

// -------------------- scratch (device globals; no allocs allowed) ---------
__device__ float g_xq[(size_t)SEQLEN * QSTRIDE];
__device__ float g_xk[(size_t)SEQLEN * KSTRIDE];
__device__ float g_xv[(size_t)SEQLEN * KSTRIDE];
__device__ float g_ao[(size_t)SEQLEN * QSTRIDE];

// -------------------- GEMM: C[M,N] = A[M,K] * B[N,K]^T --------------------
// 128x128 block, BK=16, 256 threads, 8x8 microtile per thread.
__global__ __launch_bounds__(256, 2) void gemm_nt(
    const float* __restrict__ A, const float* __restrict__ B,
    float* __restrict__ C, int M, int N, int K)
{
    __shared__ float As[16][128];
    __shared__ float Bs[16][128];

    const int tid = threadIdx.x;
    const int tx = tid & 15;
    const int ty = tid >> 4;
    const int bm = blockIdx.y << 7;
    const int bn = blockIdx.x << 7;

    const int lr = tid >> 2;          // 0..63
    const int lc = (tid & 3) << 2;    // 0,4,8,12

    const float* Ap = A + (size_t)(bm + lr) * K + lc;
    const float* Bp = B + (size_t)(bn + lr) * K + lc;
    const size_t rowskip = (size_t)64 * K;

    float acc[8][8];
#pragma unroll
    for (int i = 0; i < 8; i++)
#pragma unroll
        for (int j = 0; j < 8; j++) acc[i][j] = 0.f;

    for (int k0 = 0; k0 < K; k0 += 16) {
        float4 a0 = *(const float4*)(Ap + k0);
        float4 a1 = *(const float4*)(Ap + k0 + rowskip);
        float4 b0 = *(const float4*)(Bp + k0);
        float4 b1 = *(const float4*)(Bp + k0 + rowskip);

        As[lc + 0][lr] = a0.x; As[lc + 1][lr] = a0.y;
        As[lc + 2][lr] = a0.z; As[lc + 3][lr] = a0.w;
        As[lc + 0][lr + 64] = a1.x; As[lc + 1][lr + 64] = a1.y;
        As[lc + 2][lr + 64] = a1.z; As[lc + 3][lr + 64] = a1.w;
        Bs[lc + 0][lr] = b0.x; Bs[lc + 1][lr] = b0.y;
        Bs[lc + 2][lr] = b0.z; Bs[lc + 3][lr] = b0.w;
        Bs[lc + 0][lr + 64] = b1.x; Bs[lc + 1][lr + 64] = b1.y;
        Bs[lc + 2][lr + 64] = b1.z; Bs[lc + 3][lr + 64] = b1.w;

        __syncthreads();

#pragma unroll
        for (int kk = 0; kk < 16; kk++) {
            float a[8], b[8];
            *(float4*)&a[0] = *(const float4*)&As[kk][ty << 3];
            *(float4*)&a[4] = *(const float4*)&As[kk][(ty << 3) + 4];
            *(float4*)&b[0] = *(const float4*)&Bs[kk][tx << 3];
            *(float4*)&b[4] = *(const float4*)&Bs[kk][(tx << 3) + 4];
#pragma unroll
            for (int i = 0; i < 8; i++)
#pragma unroll
                for (int j = 0; j < 8; j++)
                    acc[i][j] = fmaf(a[i], b[j], acc[i][j]);
        }
        __syncthreads();
    }

#pragma unroll
    for (int i = 0; i < 8; i++) {
        float* Cp = C + (size_t)(bm + (ty << 3) + i) * N + bn + (tx << 3);
        *(float4*)Cp       = make_float4(acc[i][0], acc[i][1], acc[i][2], acc[i][3]);
        *(float4*)(Cp + 4) = make_float4(acc[i][4], acc[i][5], acc[i][6], acc[i][7]);
    }
}

// -------------------- RoPE on Q --------------------
__global__ void rope_q_kernel(float* __restrict__ xq,
                              const float* __restrict__ cf,
                              const float* __restrict__ sf)
{
    int idx = blockIdx.x * blockDim.x + threadIdx.x;   // SEQLEN*NHEADS*64
    if (idx >= SEQLEN * NHEADS * 64) return;
    int d = idx & 63;
    int h = (idx >> 6) & (NHEADS - 1);
    int p = idx >> 11;
    float c = cf[p * 64 + d];
    float s = sf[p * 64 + d];
    float* b = xq + ((size_t)p * NHEADS + h) * HD + 2 * d;
    float e = b[0], o = b[1];
    b[0] = e * c - o * s;
    b[1] = e * s + o * c;
}

// -------------------- RoPE on K + cache writes --------------------
__global__ void rope_k_cache_kernel(float* __restrict__ xk,
                                    const float* __restrict__ xv,
                                    const float* __restrict__ cf,
                                    const float* __restrict__ sf,
                                    float* __restrict__ ck,
                                    float* __restrict__ cv)
{
    int idx = blockIdx.x * blockDim.x + threadIdx.x;   // SEQLEN*NKV*64
    if (idx >= SEQLEN * NKV * 64) return;
    int d = idx & 63;
    int h = (idx >> 6) & (NKV - 1);
    int p = idx >> 9;
    float c = cf[p * 64 + d];
    float s = sf[p * 64 + d];
    size_t off = ((size_t)p * NKV + h) * HD + 2 * d;
    float e = xk[off], o = xk[off + 1];
    float r1 = e * c - o * s;
    float r2 = e * s + o * c;
    xk[off] = r1; xk[off + 1] = r2;
    ck[off] = r1; ck[off + 1] = r2;
    cv[off]     = xv[off];
    cv[off + 1] = xv[off + 1];
}

// -------------------- cache tail (untouched rows 2048..4095) --------------
__global__ void cache_tail_kernel(const float* __restrict__ cki,
                                  const float* __restrict__ cvi,
                                  float* __restrict__ cko,
                                  float* __restrict__ cvo)
{
    int idx = blockIdx.x * blockDim.x + threadIdx.x;
    if (idx >= (WINDOW - SEQLEN) * KSTRIDE) return;
    size_t off = (size_t)SEQLEN * KSTRIDE + idx;
    cko[off] = cki[off];
    cvo[off] = cvi[off];
}

// -------------------- Flash attention (fp32, causal) ----------------------
// grid (SEQLEN/64, NHEADS), 256 threads (16x16), BM=BN=64, D=128.
#define FLASH_SMEM_FLOATS (3 * 64 * 128 + 64 * 68)
#define FLASH_SMEM_BYTES  (FLASH_SMEM_FLOATS * 4)

__global__ __launch_bounds__(256) void flash_attn_kernel(
    const float* __restrict__ Qg, const float* __restrict__ Kg,
    const float* __restrict__ Vg, float* __restrict__ Og)
{
    extern __shared__ float sm[];
    float* Qs = sm;                 // 64*128
    float* Ks = Qs + 64 * 128;      // 64*128
    float* Vs = Ks + 64 * 128;      // 64*128
    float* Ps = Vs + 64 * 128;      // 64*68 (padded)

    const int tid = threadIdx.x;
    const int tx = tid & 15;
    const int ty = tid >> 4;
    const int qb = blockIdx.x;
    const int h  = blockIdx.y;
    const int kvh = h >> 2;
    const int q0 = qb << 6;

    // load Q tile
    {
        const float4* src = (const float4*)(Qg + (size_t)q0 * QSTRIDE + h * HD);
        float4* dst = (float4*)Qs;
        for (int i = tid; i < 64 * 32; i += 256) {
            int r = i >> 5, d4 = i & 31;
            dst[r * 32 + d4] = src[(size_t)r * (QSTRIDE / 4) + d4];
        }
    }

    float m[4], l[4], o[4][8];
#pragma unroll
    for (int i = 0; i < 4; i++) {
        m[i] = -1e30f; l[i] = 0.f;
#pragma unroll
        for (int j = 0; j < 8; j++) o[i][j] = 0.f;
    }
    __syncthreads();

    for (int kb = 0; kb <= qb; kb++) {
        const int k0 = kb << 6;
        {
            const float4* ksrc = (const float4*)(Kg + (size_t)k0 * KSTRIDE + kvh * HD);
            const float4* vsrc = (const float4*)(Vg + (size_t)k0 * KSTRIDE + kvh * HD);
            float4* kd = (float4*)Ks;
            float4* vd = (float4*)Vs;
            for (int i = tid; i < 64 * 32; i += 256) {
                int r = i >> 5, d4 = i & 31;
                kd[r * 32 + d4] = ksrc[(size_t)r * (KSTRIDE / 4) + d4];
                vd[r * 32 + d4] = vsrc[(size_t)r * (KSTRIDE / 4) + d4];
            }
        }
        __syncthreads();

        // S = Q K^T : 4x4 per thread
        float s[4][4];
#pragma unroll
        for (int i = 0; i < 4; i++)
#pragma unroll
            for (int j = 0; j < 4; j++) s[i][j] = 0.f;

        const float4* Q4 = (const float4*)Qs;
        const float4* K4 = (const float4*)Ks;
#pragma unroll 4
        for (int d4 = 0; d4 < 32; d4++) {
            float4 qa[4], kv[4];
#pragma unroll
            for (int i = 0; i < 4; i++) qa[i] = Q4[(ty * 4 + i) * 32 + d4];
#pragma unroll
            for (int j = 0; j < 4; j++) kv[j] = K4[(tx * 4 + j) * 32 + d4];
#pragma unroll
            for (int i = 0; i < 4; i++)
#pragma unroll
                for (int j = 0; j < 4; j++) {
                    s[i][j] = fmaf(qa[i].x, kv[j].x, s[i][j]);
                    s[i][j] = fmaf(qa[i].y, kv[j].y, s[i][j]);
                    s[i][j] = fmaf(qa[i].z, kv[j].z, s[i][j]);
                    s[i][j] = fmaf(qa[i].w, kv[j].w, s[i][j]);
                }
        }

        // scale + causal mask
#pragma unroll
        for (int i = 0; i < 4; i++) {
            int qi = q0 + ty * 4 + i;
#pragma unroll
            for (int j = 0; j < 4; j++) {
                int kj = k0 + tx * 4 + j;
                s[i][j] = (kj <= qi) ? s[i][j] * ATT_SCALE : -1e30f;
            }
        }

        // online softmax (row groups = 16 consecutive lanes)
#pragma unroll
        for (int i = 0; i < 4; i++) {
            float mt = fmaxf(fmaxf(s[i][0], s[i][1]), fmaxf(s[i][2], s[i][3]));
            mt = fmaxf(mt, __shfl_xor_sync(0xffffffffu, mt, 8, 16));
            mt = fmaxf(mt, __shfl_xor_sync(0xffffffffu, mt, 4, 16));
            mt = fmaxf(mt, __shfl_xor_sync(0xffffffffu, mt, 2, 16));
            mt = fmaxf(mt, __shfl_xor_sync(0xffffffffu, mt, 1, 16));
            float mn = fmaxf(m[i], mt);
            float corr = __expf(m[i] - mn);
            float rs = 0.f;
#pragma unroll
            for (int j = 0; j < 4; j++) {
                s[i][j] = __expf(s[i][j] - mn);
                rs += s[i][j];
            }
            rs += __shfl_xor_sync(0xffffffffu, rs, 8, 16);
            rs += __shfl_xor_sync(0xffffffffu, rs, 4, 16);
            rs += __shfl_xor_sync(0xffffffffu, rs, 2, 16);
            rs += __shfl_xor_sync(0xffffffffu, rs, 1, 16);
            l[i] = l[i] * corr + rs;
            m[i] = mn;
#pragma unroll
            for (int j = 0; j < 8; j++) o[i][j] *= corr;
            *(float4*)&Ps[(ty * 4 + i) * 68 + tx * 4] =
                make_float4(s[i][0], s[i][1], s[i][2], s[i][3]);
        }
        __syncthreads();

        // O += P V : cols tx*8..+7, rows ty*4..+3
        const float4* V4 = (const float4*)Vs;
#pragma unroll 4
        for (int k = 0; k < 64; k++) {
            float4 v0 = V4[k * 32 + tx * 2];
            float4 v1 = V4[k * 32 + tx * 2 + 1];
#pragma unroll
            for (int i = 0; i < 4; i++) {
                float p = Ps[(ty * 4 + i) * 68 + k];
                o[i][0] = fmaf(p, v0.x, o[i][0]);
                o[i][1] = fmaf(p, v0.y, o[i][1]);
                o[i][2] = fmaf(p, v0.z, o[i][2]);
                o[i][3] = fmaf(p, v0.w, o[i][3]);
                o[i][4] = fmaf(p, v1.x, o[i][4]);
                o[i][5] = fmaf(p, v1.y, o[i][5]);
                o[i][6] = fmaf(p, v1.z, o[i][6]);
                o[i][7] = fmaf(p, v1.w, o[i][7]);
            }
        }
        __syncthreads();
    }

    // epilogue: normalize + store
#pragma unroll
    for (int i = 0; i < 4; i++) {
        float inv = 1.0f / l[i];
        float* op = Og + (size_t)(q0 + ty * 4 + i) * QSTRIDE + h * HD + tx * 8;
        *(float4*)op       = make_float4(o[i][0] * inv, o[i][1] * inv, o[i][2] * inv, o[i][3] * inv);
        *(float4*)(op + 4) = make_float4(o[i][4] * inv, o[i][5] * inv, o[i][6] * inv, o[i][7] * inv);
    }
}

// -------------------- launch --------------------
extern "C" void kernel_launch(void* const* d_in, const int* in_sizes, int n_in,
                              void* d_out, int out_size)
{
    (void)in_sizes; (void)n_in; (void)out_size;
    const float* x   = (const float*)d_in[0];
    const float* cf  = (const float*)d_in[1];
    const float* sf  = (const float*)d_in[2];
    // d_in[3] positions, d_in[4] mask: analytically known, unused
    const float* cki = (const float*)d_in[5];
    const float* cvi = (const float*)d_in[6];
    const float* wq  = (const float*)d_in[7];
    const float* wk  = (const float*)d_in[8];
    const float* wv  = (const float*)d_in[9];
    const float* wo  = (const float*)d_in[10];

    float* out    = (float*)d_out;                       // [2048, 4096]
    float* out_ck = out + (size_t)SEQLEN * DIM;          // [4096, 8, 128]
    float* out_cv = out_ck + (size_t)WINDOW * KSTRIDE;   // [4096, 8, 128]

    float *xq, *xk, *xv, *ao;
    cudaGetSymbolAddress((void**)&xq, g_xq);
    cudaGetSymbolAddress((void**)&xk, g_xk);
    cudaGetSymbolAddress((void**)&xv, g_xv);
    cudaGetSymbolAddress((void**)&ao, g_ao);

    cudaFuncSetAttribute(flash_attn_kernel,
                         cudaFuncAttributeMaxDynamicSharedMemorySize,
                         FLASH_SMEM_BYTES);

    dim3 blk(256);
    // QKV projections
    gemm_nt<<<dim3(DIM / 128, SEQLEN / 128), blk>>>(x, wq, xq, SEQLEN, DIM, DIM);
    gemm_nt<<<dim3(KSTRIDE / 128, SEQLEN / 128), blk>>>(x, wk, xk, SEQLEN, KSTRIDE, DIM);
    gemm_nt<<<dim3(KSTRIDE / 128, SEQLEN / 128), blk>>>(x, wv, xv, SEQLEN, KSTRIDE, DIM);
    // RoPE + cache
    rope_q_kernel<<<(SEQLEN * NHEADS * 64) / 256, 256>>>(xq, cf, sf);
    rope_k_cache_kernel<<<(SEQLEN * NKV * 64) / 256, 256>>>(xk, xv, cf, sf, out_ck, out_cv);
    cache_tail_kernel<<<((WINDOW - SEQLEN) * KSTRIDE) / 256, 256>>>(cki, cvi, out_ck, out_cv);
    // Attention
    flash_attn_kernel<<<dim3(SEQLEN / 64, NHEADS), 256, FLASH_SMEM_BYTES>>>(xq, xk, xv, ao);
    // Output projection
    gemm_nt<<<dim3(DIM / 128, SEQLEN / 128), blk>>>(ao, wo, out, SEQLEN, DIM, DIM);
}

// round 4
// speedup vs baseline: 1.4360x; 1.4360x over previous
#include <cuda_runtime.h>
#include <cuda_bf16.h>
#include <cstdint>
#include <math.h>

#define SEQLEN   2048
#define DIM      4096
#define NHEADS   32
#define NKV      8
#define HD       128
#define WINDOW   4096
#define QSTRIDE  (NHEADS * HD)   // 4096
#define KSTRIDE  (NKV * HD)      // 1024
#define ATT_SCALE 0.08838834764831843f  // 128^-0.5

// ==================== scratch (device globals; no allocs allowed) ==========
__device__ float g_xq[(size_t)SEQLEN * QSTRIDE];
__device__ float g_xk[(size_t)SEQLEN * KSTRIDE];
__device__ float g_xv[(size_t)SEQLEN * KSTRIDE];
__device__ float g_ao[(size_t)SEQLEN * QSTRIDE];

__device__ __nv_bfloat16 g_xh [(size_t)SEQLEN * DIM];
__device__ __nv_bfloat16 g_xl [(size_t)SEQLEN * DIM];
__device__ __nv_bfloat16 g_wqh[(size_t)QSTRIDE * DIM];
__device__ __nv_bfloat16 g_wql[(size_t)QSTRIDE * DIM];
__device__ __nv_bfloat16 g_wkh[(size_t)KSTRIDE * DIM];
__device__ __nv_bfloat16 g_wkl[(size_t)KSTRIDE * DIM];
__device__ __nv_bfloat16 g_wvh[(size_t)KSTRIDE * DIM];
__device__ __nv_bfloat16 g_wvl[(size_t)KSTRIDE * DIM];
__device__ __nv_bfloat16 g_woh[(size_t)DIM * QSTRIDE];
__device__ __nv_bfloat16 g_wol[(size_t)DIM * QSTRIDE];
__device__ __nv_bfloat16 g_aoh[(size_t)SEQLEN * QSTRIDE];
__device__ __nv_bfloat16 g_aol[(size_t)SEQLEN * QSTRIDE];

// ==================== fp32 -> bf16 hi/lo split ==============================
__global__ void split_kernel(const float* __restrict__ src,
                             __nv_bfloat16* __restrict__ hi,
                             __nv_bfloat16* __restrict__ lo, int n4)
{
    int i = blockIdx.x * blockDim.x + threadIdx.x;
    if (i >= n4) return;
    float4 v = ((const float4*)src)[i];
    __nv_bfloat16 h0 = __float2bfloat16_rn(v.x);
    __nv_bfloat16 h1 = __float2bfloat16_rn(v.y);
    __nv_bfloat16 h2 = __float2bfloat16_rn(v.z);
    __nv_bfloat16 h3 = __float2bfloat16_rn(v.w);
    __nv_bfloat16 l0 = __float2bfloat16_rn(v.x - __bfloat162float(h0));
    __nv_bfloat16 l1 = __float2bfloat16_rn(v.y - __bfloat162float(h1));
    __nv_bfloat16 l2 = __float2bfloat16_rn(v.z - __bfloat162float(h2));
    __nv_bfloat16 l3 = __float2bfloat16_rn(v.w - __bfloat162float(h3));
    __nv_bfloat162* H = (__nv_bfloat162*)hi;
    __nv_bfloat162* L = (__nv_bfloat162*)lo;
    H[2 * i]     = __nv_bfloat162(h0, h1);
    H[2 * i + 1] = __nv_bfloat162(h2, h3);
    L[2 * i]     = __nv_bfloat162(l0, l1);
    L[2 * i + 1] = __nv_bfloat162(l2, l3);
}

// ==================== HMMA helpers ==========================================
__device__ __forceinline__ void mma16816(float* c, const uint32_t* a, const uint32_t* b) {
    asm volatile(
        "mma.sync.aligned.m16n8k16.row.col.f32.bf16.bf16.f32 "
        "{%0,%1,%2,%3}, {%4,%5,%6,%7}, {%8,%9}, {%0,%1,%2,%3};"
        : "+f"(c[0]), "+f"(c[1]), "+f"(c[2]), "+f"(c[3])
        : "r"(a[0]), "r"(a[1]), "r"(a[2]), "r"(a[3]), "r"(b[0]), "r"(b[1]));
}

__device__ __forceinline__ void cp_async16(void* smem_dst, const void* gmem_src) {
    uint32_t sa;
    asm("{ .reg .u64 t; cvta.to.shared.u64 t, %1; cvt.u32.u64 %0, t; }"
        : "=r"(sa) : "l"(smem_dst));
    asm volatile("cp.async.cg.shared.global [%0], [%1], 16;" :: "r"(sa), "l"(gmem_src));
}
#define CP_COMMIT() asm volatile("cp.async.commit_group;" ::: "memory")
#define CP_WAIT0()  asm volatile("cp.async.wait_group 0;" ::: "memory")

// ==================== HMMA bf16x3 GEMM: C[M,N] = A[M,K] @ B[N,K]^T ==========
// 128x128 CTA tile, BK=32, 8 warps (warp tile 64x32), 2-stage cp.async.
#define GPAD     40                 // bf16 row stride (conflict-free)
#define SUBT_B   (128 * GPAD * 2)   // 10240 bytes per sub-tile
#define STAGE_B  (4 * SUBT_B)       // Ahi, Alo, Bhi, Blo
#define GSMEM_BYTES (2 * STAGE_B)   // 81920

__global__ __launch_bounds__(256, 1) void gemm_mma(
    const __nv_bfloat16* __restrict__ Ah, const __nv_bfloat16* __restrict__ Al,
    const __nv_bfloat16* __restrict__ Bh, const __nv_bfloat16* __restrict__ Bl,
    float* __restrict__ C, int M, int N, int K)
{
    extern __shared__ char sm[];
    const int tid  = threadIdx.x;
    const int wid  = tid >> 5;
    const int lane = tid & 31;
    const int g    = lane >> 2;      // group id 0..7
    const int tg   = lane & 3;       // thread-in-group 0..3
    const int wm   = wid & 1;        // warp row (2 x 64)
    const int wn   = wid >> 1;       // warp col (4 x 32)
    const int bm   = blockIdx.y << 7;
    const int bn   = blockIdx.x << 7;

    const __nv_bfloat16* gsrc[4] = { Ah, Al, Bh, Bl };
    const int row0[4] = { bm, bm, bn, bn };

    // ---- async tile loader: stage s, k-offset k0 ----
    auto load_stage = [&](int s, int k0) {
        char* base = sm + s * STAGE_B;
#pragma unroll
        for (int t = 0; t < 8; t++) {
            int id  = tid + (t << 8);        // 0..2047
            int sub = id >> 9;               // which sub-tile
            int idx = id & 511;
            int r   = idx >> 2;              // 0..127
            int c   = idx & 3;               // 0..3 (16B chunks)
            char* dst = base + sub * SUBT_B + r * (GPAD * 2) + c * 16;
            const __nv_bfloat16* src =
                gsrc[sub] + (size_t)(row0[sub] + r) * K + k0 + c * 8;
            cp_async16(dst, src);
        }
        CP_COMMIT();
    };

    float acc[4][4][4];
#pragma unroll
    for (int m = 0; m < 4; m++)
#pragma unroll
        for (int n = 0; n < 4; n++)
#pragma unroll
            for (int k = 0; k < 4; k++) acc[m][n][k] = 0.f;

    const int NIT = K >> 5;   // BK = 32
    load_stage(0, 0);

    for (int it = 0; it < NIT; it++) {
        CP_WAIT0();
        __syncthreads();
        if (it + 1 < NIT) load_stage((it + 1) & 1, (it + 1) << 5);

        const char* base = sm + (it & 1) * STAGE_B;
        const __nv_bfloat16* Ahs = (const __nv_bfloat16*)(base + 0 * SUBT_B);
        const __nv_bfloat16* Als = (const __nv_bfloat16*)(base + 1 * SUBT_B);
        const __nv_bfloat16* Bhs = (const __nv_bfloat16*)(base + 2 * SUBT_B);
        const __nv_bfloat16* Bls = (const __nv_bfloat16*)(base + 3 * SUBT_B);

#pragma unroll
        for (int ks = 0; ks < 32; ks += 16) {
            // B fragments (4 n-tiles x {b0,b1} x {hi,lo})
            uint32_t bh[4][2], bl[4][2];
#pragma unroll
            for (int n = 0; n < 4; n++) {
                int nr = wn * 32 + n * 8 + g;
                bh[n][0] = *(const uint32_t*)&Bhs[nr * GPAD + ks + 2 * tg];
                bh[n][1] = *(const uint32_t*)&Bhs[nr * GPAD + ks + 8 + 2 * tg];
                bl[n][0] = *(const uint32_t*)&Bls[nr * GPAD + ks + 2 * tg];
                bl[n][1] = *(const uint32_t*)&Bls[nr * GPAD + ks + 8 + 2 * tg];
            }
#pragma unroll
            for (int m = 0; m < 4; m++) {
                int mr = wm * 64 + m * 16;
                uint32_t ah[4], al[4];
                ah[0] = *(const uint32_t*)&Ahs[(mr + g)     * GPAD + ks + 2 * tg];
                ah[1] = *(const uint32_t*)&Ahs[(mr + 8 + g) * GPAD + ks + 2 * tg];
                ah[2] = *(const uint32_t*)&Ahs[(mr + g)     * GPAD + ks + 8 + 2 * tg];
                ah[3] = *(const uint32_t*)&Ahs[(mr + 8 + g) * GPAD + ks + 8 + 2 * tg];
                al[0] = *(const uint32_t*)&Als[(mr + g)     * GPAD + ks + 2 * tg];
                al[1] = *(const uint32_t*)&Als[(mr + 8 + g) * GPAD + ks + 2 * tg];
                al[2] = *(const uint32_t*)&Als[(mr + g)     * GPAD + ks + 8 + 2 * tg];
                al[3] = *(const uint32_t*)&Als[(mr + 8 + g) * GPAD + ks + 8 + 2 * tg];
#pragma unroll
                for (int n = 0; n < 4; n++) {
                    mma16816(acc[m][n], ah, bh[n]);
                    mma16816(acc[m][n], ah, bl[n]);
                    mma16816(acc[m][n], al, bh[n]);
                }
            }
        }
        __syncthreads();
    }

    // ---- epilogue ----
#pragma unroll
    for (int m = 0; m < 4; m++) {
        int r0 = bm + wm * 64 + m * 16 + g;
#pragma unroll
        for (int n = 0; n < 4; n++) {
            int col = bn + wn * 32 + n * 8 + 2 * tg;
            *(float2*)&C[(size_t)r0 * N + col] =
                make_float2(acc[m][n][0], acc[m][n][1]);
            *(float2*)&C[(size_t)(r0 + 8) * N + col] =
                make_float2(acc[m][n][2], acc[m][n][3]);
        }
    }
}

// ==================== RoPE on Q =============================================
__global__ void rope_q_kernel(float* __restrict__ xq,
                              const float* __restrict__ cf,
                              const float* __restrict__ sf)
{
    int idx = blockIdx.x * blockDim.x + threadIdx.x;
    if (idx >= SEQLEN * NHEADS * 64) return;
    int d = idx & 63;
    int h = (idx >> 6) & (NHEADS - 1);
    int p = idx >> 11;
    float c = cf[p * 64 + d];
    float s = sf[p * 64 + d];
    float* b = xq + ((size_t)p * NHEADS + h) * HD + 2 * d;
    float e = b[0], o = b[1];
    b[0] = e * c - o * s;
    b[1] = e * s + o * c;
}

// ==================== RoPE on K + cache writes ==============================
__global__ void rope_k_cache_kernel(float* __restrict__ xk,
                                    const float* __restrict__ xv,
                                    const float* __restrict__ cf,
                                    const float* __restrict__ sf,
                                    float* __restrict__ ck,
                                    float* __restrict__ cv)
{
    int idx = blockIdx.x * blockDim.x + threadIdx.x;
    if (idx >= SEQLEN * NKV * 64) return;
    int d = idx & 63;
    int h = (idx >> 6) & (NKV - 1);
    int p = idx >> 9;
    float c = cf[p * 64 + d];
    float s = sf[p * 64 + d];
    size_t off = ((size_t)p * NKV + h) * HD + 2 * d;
    float e = xk[off], o = xk[off + 1];
    float r1 = e * c - o * s;
    float r2 = e * s + o * c;
    xk[off] = r1; xk[off + 1] = r2;
    ck[off] = r1; ck[off + 1] = r2;
    cv[off]     = xv[off];
    cv[off + 1] = xv[off + 1];
}

// ==================== cache tail ============================================
__global__ void cache_tail_kernel(const float* __restrict__ cki,
                                  const float* __restrict__ cvi,
                                  float* __restrict__ cko,
                                  float* __restrict__ cvo)
{
    int idx = blockIdx.x * blockDim.x + threadIdx.x;
    if (idx >= (WINDOW - SEQLEN) * KSTRIDE) return;
    size_t off = (size_t)SEQLEN * KSTRIDE + idx;
    cko[off] = cki[off];
    cvo[off] = cvi[off];
}

// ==================== Flash attention (fp32, causal) ========================
#define FLASH_SMEM_FLOATS (3 * 64 * 128 + 64 * 68)
#define FLASH_SMEM_BYTES  (FLASH_SMEM_FLOATS * 4)

__global__ __launch_bounds__(256) void flash_attn_kernel(
    const float* __restrict__ Qg, const float* __restrict__ Kg,
    const float* __restrict__ Vg, float* __restrict__ Og)
{
    extern __shared__ float smf[];
    float* Qs = smf;
    float* Ks = Qs + 64 * 128;
    float* Vs = Ks + 64 * 128;
    float* Ps = Vs + 64 * 128;

    const int tid = threadIdx.x;
    const int tx = tid & 15;
    const int ty = tid >> 4;
    const int qb = blockIdx.x;
    const int h  = blockIdx.y;
    const int kvh = h >> 2;
    const int q0 = qb << 6;

    {
        const float4* src = (const float4*)(Qg + (size_t)q0 * QSTRIDE + h * HD);
        float4* dst = (float4*)Qs;
        for (int i = tid; i < 64 * 32; i += 256) {
            int r = i >> 5, d4 = i & 31;
            dst[r * 32 + d4] = src[(size_t)r * (QSTRIDE / 4) + d4];
        }
    }

    float m[4], l[4], o[4][8];
#pragma unroll
    for (int i = 0; i < 4; i++) {
        m[i] = -1e30f; l[i] = 0.f;
#pragma unroll
        for (int j = 0; j < 8; j++) o[i][j] = 0.f;
    }
    __syncthreads();

    for (int kb = 0; kb <= qb; kb++) {
        const int k0 = kb << 6;
        {
            const float4* ksrc = (const float4*)(Kg + (size_t)k0 * KSTRIDE + kvh * HD);
            const float4* vsrc = (const float4*)(Vg + (size_t)k0 * KSTRIDE + kvh * HD);
            float4* kd = (float4*)Ks;
            float4* vd = (float4*)Vs;
            for (int i = tid; i < 64 * 32; i += 256) {
                int r = i >> 5, d4 = i & 31;
                kd[r * 32 + d4] = ksrc[(size_t)r * (KSTRIDE / 4) + d4];
                vd[r * 32 + d4] = vsrc[(size_t)r * (KSTRIDE / 4) + d4];
            }
        }
        __syncthreads();

        float s[4][4];
#pragma unroll
        for (int i = 0; i < 4; i++)
#pragma unroll
            for (int j = 0; j < 4; j++) s[i][j] = 0.f;

        const float4* Q4 = (const float4*)Qs;
        const float4* K4 = (const float4*)Ks;
#pragma unroll 4
        for (int d4 = 0; d4 < 32; d4++) {
            float4 qa[4], kv[4];
#pragma unroll
            for (int i = 0; i < 4; i++) qa[i] = Q4[(ty * 4 + i) * 32 + d4];
#pragma unroll
            for (int j = 0; j < 4; j++) kv[j] = K4[(tx * 4 + j) * 32 + d4];
#pragma unroll
            for (int i = 0; i < 4; i++)
#pragma unroll
                for (int j = 0; j < 4; j++) {
                    s[i][j] = fmaf(qa[i].x, kv[j].x, s[i][j]);
                    s[i][j] = fmaf(qa[i].y, kv[j].y, s[i][j]);
                    s[i][j] = fmaf(qa[i].z, kv[j].z, s[i][j]);
                    s[i][j] = fmaf(qa[i].w, kv[j].w, s[i][j]);
                }
        }

#pragma unroll
        for (int i = 0; i < 4; i++) {
            int qi = q0 + ty * 4 + i;
#pragma unroll
            for (int j = 0; j < 4; j++) {
                int kj = k0 + tx * 4 + j;
                s[i][j] = (kj <= qi) ? s[i][j] * ATT_SCALE : -1e30f;
            }
        }

#pragma unroll
        for (int i = 0; i < 4; i++) {
            float mt = fmaxf(fmaxf(s[i][0], s[i][1]), fmaxf(s[i][2], s[i][3]));
            mt = fmaxf(mt, __shfl_xor_sync(0xffffffffu, mt, 8, 16));
            mt = fmaxf(mt, __shfl_xor_sync(0xffffffffu, mt, 4, 16));
            mt = fmaxf(mt, __shfl_xor_sync(0xffffffffu, mt, 2, 16));
            mt = fmaxf(mt, __shfl_xor_sync(0xffffffffu, mt, 1, 16));
            float mn = fmaxf(m[i], mt);
            float corr = __expf(m[i] - mn);
            float rs = 0.f;
#pragma unroll
            for (int j = 0; j < 4; j++) {
                s[i][j] = __expf(s[i][j] - mn);
                rs += s[i][j];
            }
            rs += __shfl_xor_sync(0xffffffffu, rs, 8, 16);
            rs += __shfl_xor_sync(0xffffffffu, rs, 4, 16);
            rs += __shfl_xor_sync(0xffffffffu, rs, 2, 16);
            rs += __shfl_xor_sync(0xffffffffu, rs, 1, 16);
            l[i] = l[i] * corr + rs;
            m[i] = mn;
#pragma unroll
            for (int j = 0; j < 8; j++) o[i][j] *= corr;
            *(float4*)&Ps[(ty * 4 + i) * 68 + tx * 4] =
                make_float4(s[i][0], s[i][1], s[i][2], s[i][3]);
        }
        __syncthreads();

        const float4* V4 = (const float4*)Vs;
#pragma unroll 4
        for (int k = 0; k < 64; k++) {
            float4 v0 = V4[k * 32 + tx * 2];
            float4 v1 = V4[k * 32 + tx * 2 + 1];
#pragma unroll
            for (int i = 0; i < 4; i++) {
                float p = Ps[(ty * 4 + i) * 68 + k];
                o[i][0] = fmaf(p, v0.x, o[i][0]);
                o[i][1] = fmaf(p, v0.y, o[i][1]);
                o[i][2] = fmaf(p, v0.z, o[i][2]);
                o[i][3] = fmaf(p, v0.w, o[i][3]);
                o[i][4] = fmaf(p, v1.x, o[i][4]);
                o[i][5] = fmaf(p, v1.y, o[i][5]);
                o[i][6] = fmaf(p, v1.z, o[i][6]);
                o[i][7] = fmaf(p, v1.w, o[i][7]);
            }
        }
        __syncthreads();
    }

#pragma unroll
    for (int i = 0; i < 4; i++) {
        float inv = 1.0f / l[i];
        float* op = Og + (size_t)(q0 + ty * 4 + i) * QSTRIDE + h * HD + tx * 8;
        *(float4*)op       = make_float4(o[i][0] * inv, o[i][1] * inv, o[i][2] * inv, o[i][3] * inv);
        *(float4*)(op + 4) = make_float4(o[i][4] * inv, o[i][5] * inv, o[i][6] * inv, o[i][7] * inv);
    }
}

// ==================== launch ================================================
extern "C" void kernel_launch(void* const* d_in, const int* in_sizes, int n_in,
                              void* d_out, int out_size)
{
    (void)in_sizes; (void)n_in; (void)out_size;
    const float* x   = (const float*)d_in[0];
    const float* cf  = (const float*)d_in[1];
    const float* sf  = (const float*)d_in[2];
    const float* cki = (const float*)d_in[5];
    const float* cvi = (const float*)d_in[6];
    const float* wq  = (const float*)d_in[7];
    const float* wk  = (const float*)d_in[8];
    const float* wv  = (const float*)d_in[9];
    const float* wo  = (const float*)d_in[10];

    float* out    = (float*)d_out;
    float* out_ck = out + (size_t)SEQLEN * DIM;
    float* out_cv = out_ck + (size_t)WINDOW * KSTRIDE;

    float *xq, *xk, *xv, *ao;
    cudaGetSymbolAddress((void**)&xq, g_xq);
    cudaGetSymbolAddress((void**)&xk, g_xk);
    cudaGetSymbolAddress((void**)&xv, g_xv);
    cudaGetSymbolAddress((void**)&ao, g_ao);
    __nv_bfloat16 *xh, *xl, *wqh, *wql, *wkh, *wkl, *wvh, *wvl, *woh, *wol, *aoh, *aol;
    cudaGetSymbolAddress((void**)&xh,  g_xh);
    cudaGetSymbolAddress((void**)&xl,  g_xl);
    cudaGetSymbolAddress((void**)&wqh, g_wqh);
    cudaGetSymbolAddress((void**)&wql, g_wql);
    cudaGetSymbolAddress((void**)&wkh, g_wkh);
    cudaGetSymbolAddress((void**)&wkl, g_wkl);
    cudaGetSymbolAddress((void**)&wvh, g_wvh);
    cudaGetSymbolAddress((void**)&wvl, g_wvl);
    cudaGetSymbolAddress((void**)&woh, g_woh);
    cudaGetSymbolAddress((void**)&wol, g_wol);
    cudaGetSymbolAddress((void**)&aoh, g_aoh);
    cudaGetSymbolAddress((void**)&aol, g_aol);

    cudaFuncSetAttribute(flash_attn_kernel,
                         cudaFuncAttributeMaxDynamicSharedMemorySize, FLASH_SMEM_BYTES);
    cudaFuncSetAttribute(gemm_mma,
                         cudaFuncAttributeMaxDynamicSharedMemorySize, GSMEM_BYTES);

    // splits (x + weights)
    {
        int n;
        n = SEQLEN * DIM / 4;      split_kernel<<<(n + 255) / 256, 256>>>(x,  xh,  xl,  n);
        n = QSTRIDE * DIM / 4;     split_kernel<<<(n + 255) / 256, 256>>>(wq, wqh, wql, n);
        n = KSTRIDE * DIM / 4;     split_kernel<<<(n + 255) / 256, 256>>>(wk, wkh, wkl, n);
        n = KSTRIDE * DIM / 4;     split_kernel<<<(n + 255) / 256, 256>>>(wv, wvh, wvl, n);
        n = DIM * QSTRIDE / 4;     split_kernel<<<(n + 255) / 256, 256>>>(wo, woh, wol, n);
    }

    // QKV projections on HMMA (bf16x3)
    gemm_mma<<<dim3(QSTRIDE / 128, SEQLEN / 128), 256, GSMEM_BYTES>>>(xh, xl, wqh, wql, xq, SEQLEN, QSTRIDE, DIM);
    gemm_mma<<<dim3(KSTRIDE / 128, SEQLEN / 128), 256, GSMEM_BYTES>>>(xh, xl, wkh, wkl, xk, SEQLEN, KSTRIDE, DIM);
    gemm_mma<<<dim3(KSTRIDE / 128, SEQLEN / 128), 256, GSMEM_BYTES>>>(xh, xl, wvh, wvl, xv, SEQLEN, KSTRIDE, DIM);

    // RoPE + cache
    rope_q_kernel<<<(SEQLEN * NHEADS * 64) / 256, 256>>>(xq, cf, sf);
    rope_k_cache_kernel<<<(SEQLEN * NKV * 64) / 256, 256>>>(xk, xv, cf, sf, out_ck, out_cv);
    cache_tail_kernel<<<((WINDOW - SEQLEN) * KSTRIDE) / 256, 256>>>(cki, cvi, out_ck, out_cv);

    // Attention (SIMT fp32 for now)
    flash_attn_kernel<<<dim3(SEQLEN / 64, NHEADS), 256, FLASH_SMEM_BYTES>>>(xq, xk, xv, ao);

    // Output projection on HMMA
    {
        int n = SEQLEN * QSTRIDE / 4;
        split_kernel<<<(n + 255) / 256, 256>>>(ao, aoh, aol, n);
    }
    gemm_mma<<<dim3(DIM / 128, SEQLEN / 128), 256, GSMEM_BYTES>>>(aoh, aol, woh, wol, out, SEQLEN, DIM, DIM);
}

// round 5
// speedup vs baseline: 1.5039x; 1.0473x over previous
#include <cuda_runtime.h>
#include <cuda_bf16.h>
#include <cstdint>
#include <math.h>

#define SEQLEN   2048
#define DIM      4096
#define NHEADS   32
#define NKV      8
#define HD       128
#define WINDOW   4096
#define QSTRIDE  (NHEADS * HD)   // 4096
#define KSTRIDE  (NKV * HD)      // 1024
#define ATT_SCALE 0.08838834764831843f  // 128^-0.5

// ==================== scratch (device globals; no allocs allowed) ==========
__device__ float g_xq[(size_t)SEQLEN * QSTRIDE];
__device__ float g_xk[(size_t)SEQLEN * KSTRIDE];
__device__ float g_xv[(size_t)SEQLEN * KSTRIDE];
__device__ float g_ao[(size_t)SEQLEN * QSTRIDE];

__device__ __nv_bfloat16 g_xh [(size_t)SEQLEN * DIM];
__device__ __nv_bfloat16 g_xl [(size_t)SEQLEN * DIM];
__device__ __nv_bfloat16 g_wqh[(size_t)QSTRIDE * DIM];
__device__ __nv_bfloat16 g_wql[(size_t)QSTRIDE * DIM];
__device__ __nv_bfloat16 g_wkh[(size_t)KSTRIDE * DIM];
__device__ __nv_bfloat16 g_wkl[(size_t)KSTRIDE * DIM];
__device__ __nv_bfloat16 g_wvh[(size_t)KSTRIDE * DIM];
__device__ __nv_bfloat16 g_wvl[(size_t)KSTRIDE * DIM];
__device__ __nv_bfloat16 g_woh[(size_t)DIM * QSTRIDE];
__device__ __nv_bfloat16 g_wol[(size_t)DIM * QSTRIDE];
__device__ __nv_bfloat16 g_aoh[(size_t)SEQLEN * QSTRIDE];
__device__ __nv_bfloat16 g_aol[(size_t)SEQLEN * QSTRIDE];

// ==================== fp32 -> bf16 hi/lo split ==============================
__global__ void split_kernel(const float* __restrict__ src,
                             __nv_bfloat16* __restrict__ hi,
                             __nv_bfloat16* __restrict__ lo, int n4)
{
    int i = blockIdx.x * blockDim.x + threadIdx.x;
    if (i >= n4) return;
    float4 v = ((const float4*)src)[i];
    __nv_bfloat16 h0 = __float2bfloat16_rn(v.x);
    __nv_bfloat16 h1 = __float2bfloat16_rn(v.y);
    __nv_bfloat16 h2 = __float2bfloat16_rn(v.z);
    __nv_bfloat16 h3 = __float2bfloat16_rn(v.w);
    __nv_bfloat16 l0 = __float2bfloat16_rn(v.x - __bfloat162float(h0));
    __nv_bfloat16 l1 = __float2bfloat16_rn(v.y - __bfloat162float(h1));
    __nv_bfloat16 l2 = __float2bfloat16_rn(v.z - __bfloat162float(h2));
    __nv_bfloat16 l3 = __float2bfloat16_rn(v.w - __bfloat162float(h3));
    __nv_bfloat162* H = (__nv_bfloat162*)hi;
    __nv_bfloat162* L = (__nv_bfloat162*)lo;
    H[2 * i]     = __nv_bfloat162(h0, h1);
    H[2 * i + 1] = __nv_bfloat162(h2, h3);
    L[2 * i]     = __nv_bfloat162(l0, l1);
    L[2 * i + 1] = __nv_bfloat162(l2, l3);
}

// ==================== HMMA helpers ==========================================
__device__ __forceinline__ void mma16816(float* c, const uint32_t* a, const uint32_t* b) {
    asm volatile(
        "mma.sync.aligned.m16n8k16.row.col.f32.bf16.bf16.f32 "
        "{%0,%1,%2,%3}, {%4,%5,%6,%7}, {%8,%9}, {%0,%1,%2,%3};"
        : "+f"(c[0]), "+f"(c[1]), "+f"(c[2]), "+f"(c[3])
        : "r"(a[0]), "r"(a[1]), "r"(a[2]), "r"(a[3]), "r"(b[0]), "r"(b[1]));
}

__device__ __forceinline__ void cp_async16(void* smem_dst, const void* gmem_src) {
    uint32_t sa;
    asm("{ .reg .u64 t; cvta.to.shared.u64 t, %1; cvt.u32.u64 %0, t; }"
        : "=r"(sa) : "l"(smem_dst));
    asm volatile("cp.async.cg.shared.global [%0], [%1], 16;" :: "r"(sa), "l"(gmem_src));
}
#define CP_COMMIT() asm volatile("cp.async.commit_group;" ::: "memory")
#define CP_WAIT0()  asm volatile("cp.async.wait_group 0;" ::: "memory")

// ==================== HMMA bf16x3 GEMM: C[M,N] = A[M,K] @ B[N,K]^T ==========
// 128x128 CTA tile, BK=32, 8 warps (warp tile 64x32), 2-stage cp.async.
#define GPAD     40                 // bf16 row stride (conflict-free)
#define SUBT_B   (128 * GPAD * 2)   // 10240 bytes per sub-tile
#define STAGE_B  (4 * SUBT_B)       // Ahi, Alo, Bhi, Blo
#define GSMEM_BYTES (2 * STAGE_B)   // 81920

__global__ __launch_bounds__(256, 1) void gemm_mma(
    const __nv_bfloat16* __restrict__ Ah, const __nv_bfloat16* __restrict__ Al,
    const __nv_bfloat16* __restrict__ Bh, const __nv_bfloat16* __restrict__ Bl,
    float* __restrict__ C, int M, int N, int K)
{
    extern __shared__ char sm[];
    const int tid  = threadIdx.x;
    const int wid  = tid >> 5;
    const int lane = tid & 31;
    const int g    = lane >> 2;      // group id 0..7
    const int tg   = lane & 3;       // thread-in-group 0..3
    const int wm   = wid & 1;        // warp row (2 x 64)
    const int wn   = wid >> 1;       // warp col (4 x 32)
    const int bm   = blockIdx.y << 7;
    const int bn   = blockIdx.x << 7;

    const __nv_bfloat16* gsrc[4] = { Ah, Al, Bh, Bl };
    const int row0[4] = { bm, bm, bn, bn };

    // ---- async tile loader: stage s, k-offset k0 ----
    auto load_stage = [&](int s, int k0) {
        char* base = sm + s * STAGE_B;
#pragma unroll
        for (int t = 0; t < 8; t++) {
            int id  = tid + (t << 8);        // 0..2047
            int sub = id >> 9;               // which sub-tile
            int idx = id & 511;
            int r   = idx >> 2;              // 0..127
            int c   = idx & 3;               // 0..3 (16B chunks)
            char* dst = base + sub * SUBT_B + r * (GPAD * 2) + c * 16;
            const __nv_bfloat16* src =
                gsrc[sub] + (size_t)(row0[sub] + r) * K + k0 + c * 8;
            cp_async16(dst, src);
        }
        CP_COMMIT();
    };

    float acc[4][4][4];
#pragma unroll
    for (int m = 0; m < 4; m++)
#pragma unroll
        for (int n = 0; n < 4; n++)
#pragma unroll
            for (int k = 0; k < 4; k++) acc[m][n][k] = 0.f;

    const int NIT = K >> 5;   // BK = 32
    load_stage(0, 0);

    for (int it = 0; it < NIT; it++) {
        CP_WAIT0();
        __syncthreads();
        if (it + 1 < NIT) load_stage((it + 1) & 1, (it + 1) << 5);

        const char* base = sm + (it & 1) * STAGE_B;
        const __nv_bfloat16* Ahs = (const __nv_bfloat16*)(base + 0 * SUBT_B);
        const __nv_bfloat16* Als = (const __nv_bfloat16*)(base + 1 * SUBT_B);
        const __nv_bfloat16* Bhs = (const __nv_bfloat16*)(base + 2 * SUBT_B);
        const __nv_bfloat16* Bls = (const __nv_bfloat16*)(base + 3 * SUBT_B);

#pragma unroll
        for (int ks = 0; ks < 32; ks += 16) {
            // B fragments (4 n-tiles x {b0,b1} x {hi,lo})
            uint32_t bh[4][2], bl[4][2];
#pragma unroll
            for (int n = 0; n < 4; n++) {
                int nr = wn * 32 + n * 8 + g;
                bh[n][0] = *(const uint32_t*)&Bhs[nr * GPAD + ks + 2 * tg];
                bh[n][1] = *(const uint32_t*)&Bhs[nr * GPAD + ks + 8 + 2 * tg];
                bl[n][0] = *(const uint32_t*)&Bls[nr * GPAD + ks + 2 * tg];
                bl[n][1] = *(const uint32_t*)&Bls[nr * GPAD + ks + 8 + 2 * tg];
            }
#pragma unroll
            for (int m = 0; m < 4; m++) {
                int mr = wm * 64 + m * 16;
                uint32_t ah[4], al[4];
                ah[0] = *(const uint32_t*)&Ahs[(mr + g)     * GPAD + ks + 2 * tg];
                ah[1] = *(const uint32_t*)&Ahs[(mr + 8 + g) * GPAD + ks + 2 * tg];
                ah[2] = *(const uint32_t*)&Ahs[(mr + g)     * GPAD + ks + 8 + 2 * tg];
                ah[3] = *(const uint32_t*)&Ahs[(mr + 8 + g) * GPAD + ks + 8 + 2 * tg];
                al[0] = *(const uint32_t*)&Als[(mr + g)     * GPAD + ks + 2 * tg];
                al[1] = *(const uint32_t*)&Als[(mr + 8 + g) * GPAD + ks + 2 * tg];
                al[2] = *(const uint32_t*)&Als[(mr + g)     * GPAD + ks + 8 + 2 * tg];
                al[3] = *(const uint32_t*)&Als[(mr + 8 + g) * GPAD + ks + 8 + 2 * tg];
#pragma unroll
                for (int n = 0; n < 4; n++) {
                    mma16816(acc[m][n], ah, bh[n]);
                    mma16816(acc[m][n], ah, bl[n]);
                    mma16816(acc[m][n], al, bh[n]);
                }
            }
        }
        __syncthreads();
    }

    // ---- epilogue ----
#pragma unroll
    for (int m = 0; m < 4; m++) {
        int r0 = bm + wm * 64 + m * 16 + g;
#pragma unroll
        for (int n = 0; n < 4; n++) {
            int col = bn + wn * 32 + n * 8 + 2 * tg;
            *(float2*)&C[(size_t)r0 * N + col] =
                make_float2(acc[m][n][0], acc[m][n][1]);
            *(float2*)&C[(size_t)(r0 + 8) * N + col] =
                make_float2(acc[m][n][2], acc[m][n][3]);
        }
    }
}

// ==================== RoPE on Q =============================================
__global__ void rope_q_kernel(float* __restrict__ xq,
                              const float* __restrict__ cf,
                              const float* __restrict__ sf)
{
    int idx = blockIdx.x * blockDim.x + threadIdx.x;
    if (idx >= SEQLEN * NHEADS * 64) return;
    int d = idx & 63;
    int h = (idx >> 6) & (NHEADS - 1);
    int p = idx >> 11;
    float c = cf[p * 64 + d];
    float s = sf[p * 64 + d];
    float* b = xq + ((size_t)p * NHEADS + h) * HD + 2 * d;
    float e = b[0], o = b[1];
    b[0] = e * c - o * s;
    b[1] = e * s + o * c;
}

// ==================== RoPE on K + cache writes ==============================
__global__ void rope_k_cache_kernel(float* __restrict__ xk,
                                    const float* __restrict__ xv,
                                    const float* __restrict__ cf,
                                    const float* __restrict__ sf,
                                    float* __restrict__ ck,
                                    float* __restrict__ cv)
{
    int idx = blockIdx.x * blockDim.x + threadIdx.x;
    if (idx >= SEQLEN * NKV * 64) return;
    int d = idx & 63;
    int h = (idx >> 6) & (NKV - 1);
    int p = idx >> 9;
    float c = cf[p * 64 + d];
    float s = sf[p * 64 + d];
    size_t off = ((size_t)p * NKV + h) * HD + 2 * d;
    float e = xk[off], o = xk[off + 1];
    float r1 = e * c - o * s;
    float r2 = e * s + o * c;
    xk[off] = r1; xk[off + 1] = r2;
    ck[off] = r1; ck[off + 1] = r2;
    cv[off]     = xv[off];
    cv[off + 1] = xv[off + 1];
}

// ==================== cache tail ============================================
__global__ void cache_tail_kernel(const float* __restrict__ cki,
                                  const float* __restrict__ cvi,
                                  float* __restrict__ cko,
                                  float* __restrict__ cvo)
{
    int idx = blockIdx.x * blockDim.x + threadIdx.x;
    if (idx >= (WINDOW - SEQLEN) * KSTRIDE) return;
    size_t off = (size_t)SEQLEN * KSTRIDE + idx;
    cko[off] = cki[off];
    cvo[off] = cvi[off];
}

// ==================== Flash attention (fp32, causal) ========================
#define FLASH_SMEM_FLOATS (3 * 64 * 128 + 64 * 68)
#define FLASH_SMEM_BYTES  (FLASH_SMEM_FLOATS * 4)

__global__ __launch_bounds__(256) void flash_attn_kernel(
    const float* __restrict__ Qg, const float* __restrict__ Kg,
    const float* __restrict__ Vg, float* __restrict__ Og)
{
    extern __shared__ float smf[];
    float* Qs = smf;
    float* Ks = Qs + 64 * 128;
    float* Vs = Ks + 64 * 128;
    float* Ps = Vs + 64 * 128;

    const int tid = threadIdx.x;
    const int tx = tid & 15;
    const int ty = tid >> 4;
    const int qb = blockIdx.x;
    const int h  = blockIdx.y;
    const int kvh = h >> 2;
    const int q0 = qb << 6;

    {
        const float4* src = (const float4*)(Qg + (size_t)q0 * QSTRIDE + h * HD);
        float4* dst = (float4*)Qs;
        for (int i = tid; i < 64 * 32; i += 256) {
            int r = i >> 5, d4 = i & 31;
            dst[r * 32 + d4] = src[(size_t)r * (QSTRIDE / 4) + d4];
        }
    }

    float m[4], l[4], o[4][8];
#pragma unroll
    for (int i = 0; i < 4; i++) {
        m[i] = -1e30f; l[i] = 0.f;
#pragma unroll
        for (int j = 0; j < 8; j++) o[i][j] = 0.f;
    }
    __syncthreads();

    for (int kb = 0; kb <= qb; kb++) {
        const int k0 = kb << 6;
        {
            const float4* ksrc = (const float4*)(Kg + (size_t)k0 * KSTRIDE + kvh * HD);
            const float4* vsrc = (const float4*)(Vg + (size_t)k0 * KSTRIDE + kvh * HD);
            float4* kd = (float4*)Ks;
            float4* vd = (float4*)Vs;
            for (int i = tid; i < 64 * 32; i += 256) {
                int r = i >> 5, d4 = i & 31;
                kd[r * 32 + d4] = ksrc[(size_t)r * (KSTRIDE / 4) + d4];
                vd[r * 32 + d4] = vsrc[(size_t)r * (KSTRIDE / 4) + d4];
            }
        }
        __syncthreads();

        float s[4][4];
#pragma unroll
        for (int i = 0; i < 4; i++)
#pragma unroll
            for (int j = 0; j < 4; j++) s[i][j] = 0.f;

        const float4* Q4 = (const float4*)Qs;
        const float4* K4 = (const float4*)Ks;
#pragma unroll 4
        for (int d4 = 0; d4 < 32; d4++) {
            float4 qa[4], kv[4];
#pragma unroll
            for (int i = 0; i < 4; i++) qa[i] = Q4[(ty * 4 + i) * 32 + d4];
#pragma unroll
            for (int j = 0; j < 4; j++) kv[j] = K4[(tx * 4 + j) * 32 + d4];
#pragma unroll
            for (int i = 0; i < 4; i++)
#pragma unroll
                for (int j = 0; j < 4; j++) {
                    s[i][j] = fmaf(qa[i].x, kv[j].x, s[i][j]);
                    s[i][j] = fmaf(qa[i].y, kv[j].y, s[i][j]);
                    s[i][j] = fmaf(qa[i].z, kv[j].z, s[i][j]);
                    s[i][j] = fmaf(qa[i].w, kv[j].w, s[i][j]);
                }
        }

#pragma unroll
        for (int i = 0; i < 4; i++) {
            int qi = q0 + ty * 4 + i;
#pragma unroll
            for (int j = 0; j < 4; j++) {
                int kj = k0 + tx * 4 + j;
                s[i][j] = (kj <= qi) ? s[i][j] * ATT_SCALE : -1e30f;
            }
        }

#pragma unroll
        for (int i = 0; i < 4; i++) {
            float mt = fmaxf(fmaxf(s[i][0], s[i][1]), fmaxf(s[i][2], s[i][3]));
            mt = fmaxf(mt, __shfl_xor_sync(0xffffffffu, mt, 8, 16));
            mt = fmaxf(mt, __shfl_xor_sync(0xffffffffu, mt, 4, 16));
            mt = fmaxf(mt, __shfl_xor_sync(0xffffffffu, mt, 2, 16));
            mt = fmaxf(mt, __shfl_xor_sync(0xffffffffu, mt, 1, 16));
            float mn = fmaxf(m[i], mt);
            float corr = __expf(m[i] - mn);
            float rs = 0.f;
#pragma unroll
            for (int j = 0; j < 4; j++) {
                s[i][j] = __expf(s[i][j] - mn);
                rs += s[i][j];
            }
            rs += __shfl_xor_sync(0xffffffffu, rs, 8, 16);
            rs += __shfl_xor_sync(0xffffffffu, rs, 4, 16);
            rs += __shfl_xor_sync(0xffffffffu, rs, 2, 16);
            rs += __shfl_xor_sync(0xffffffffu, rs, 1, 16);
            l[i] = l[i] * corr + rs;
            m[i] = mn;
#pragma unroll
            for (int j = 0; j < 8; j++) o[i][j] *= corr;
            *(float4*)&Ps[(ty * 4 + i) * 68 + tx * 4] =
                make_float4(s[i][0], s[i][1], s[i][2], s[i][3]);
        }
        __syncthreads();

        const float4* V4 = (const float4*)Vs;
#pragma unroll 4
        for (int k = 0; k < 64; k++) {
            float4 v0 = V4[k * 32 + tx * 2];
            float4 v1 = V4[k * 32 + tx * 2 + 1];
#pragma unroll
            for (int i = 0; i < 4; i++) {
                float p = Ps[(ty * 4 + i) * 68 + k];
                o[i][0] = fmaf(p, v0.x, o[i][0]);
                o[i][1] = fmaf(p, v0.y, o[i][1]);
                o[i][2] = fmaf(p, v0.z, o[i][2]);
                o[i][3] = fmaf(p, v0.w, o[i][3]);
                o[i][4] = fmaf(p, v1.x, o[i][4]);
                o[i][5] = fmaf(p, v1.y, o[i][5]);
                o[i][6] = fmaf(p, v1.z, o[i][6]);
                o[i][7] = fmaf(p, v1.w, o[i][7]);
            }
        }
        __syncthreads();
    }

#pragma unroll
    for (int i = 0; i < 4; i++) {
        float inv = 1.0f / l[i];
        float* op = Og + (size_t)(q0 + ty * 4 + i) * QSTRIDE + h * HD + tx * 8;
        *(float4*)op       = make_float4(o[i][0] * inv, o[i][1] * inv, o[i][2] * inv, o[i][3] * inv);
        *(float4*)(op + 4) = make_float4(o[i][4] * inv, o[i][5] * inv, o[i][6] * inv, o[i][7] * inv);
    }
}

// ==================== launch ================================================
extern "C" void kernel_launch(void* const* d_in, const int* in_sizes, int n_in,
                              void* d_out, int out_size)
{
    (void)in_sizes; (void)n_in; (void)out_size;
    const float* x   = (const float*)d_in[0];
    const float* cf  = (const float*)d_in[1];
    const float* sf  = (const float*)d_in[2];
    const float* cki = (const float*)d_in[5];
    const float* cvi = (const float*)d_in[6];
    const float* wq  = (const float*)d_in[7];
    const float* wk  = (const float*)d_in[8];
    const float* wv  = (const float*)d_in[9];
    const float* wo  = (const float*)d_in[10];

    float* out    = (float*)d_out;
    float* out_ck = out + (size_t)SEQLEN * DIM;
    float* out_cv = out_ck + (size_t)WINDOW * KSTRIDE;

    float *xq, *xk, *xv, *ao;
    cudaGetSymbolAddress((void**)&xq, g_xq);
    cudaGetSymbolAddress((void**)&xk, g_xk);
    cudaGetSymbolAddress((void**)&xv, g_xv);
    cudaGetSymbolAddress((void**)&ao, g_ao);
    __nv_bfloat16 *xh, *xl, *wqh, *wql, *wkh, *wkl, *wvh, *wvl, *woh, *wol, *aoh, *aol;
    cudaGetSymbolAddress((void**)&xh,  g_xh);
    cudaGetSymbolAddress((void**)&xl,  g_xl);
    cudaGetSymbolAddress((void**)&wqh, g_wqh);
    cudaGetSymbolAddress((void**)&wql, g_wql);
    cudaGetSymbolAddress((void**)&wkh, g_wkh);
    cudaGetSymbolAddress((void**)&wkl, g_wkl);
    cudaGetSymbolAddress((void**)&wvh, g_wvh);
    cudaGetSymbolAddress((void**)&wvl, g_wvl);
    cudaGetSymbolAddress((void**)&woh, g_woh);
    cudaGetSymbolAddress((void**)&wol, g_wol);
    cudaGetSymbolAddress((void**)&aoh, g_aoh);
    cudaGetSymbolAddress((void**)&aol, g_aol);

    cudaFuncSetAttribute(flash_attn_kernel,
                         cudaFuncAttributeMaxDynamicSharedMemorySize, FLASH_SMEM_BYTES);
    cudaFuncSetAttribute(gemm_mma,
                         cudaFuncAttributeMaxDynamicSharedMemorySize, GSMEM_BYTES);

    // splits (x + weights)
    {
        int n;
        n = SEQLEN * DIM / 4;      split_kernel<<<(n + 255) / 256, 256>>>(x,  xh,  xl,  n);
        n = QSTRIDE * DIM / 4;     split_kernel<<<(n + 255) / 256, 256>>>(wq, wqh, wql, n);
        n = KSTRIDE * DIM / 4;     split_kernel<<<(n + 255) / 256, 256>>>(wk, wkh, wkl, n);
        n = KSTRIDE * DIM / 4;     split_kernel<<<(n + 255) / 256, 256>>>(wv, wvh, wvl, n);
        n = DIM * QSTRIDE / 4;     split_kernel<<<(n + 255) / 256, 256>>>(wo, woh, wol, n);
    }

    // QKV projections on HMMA (bf16x3)
    gemm_mma<<<dim3(QSTRIDE / 128, SEQLEN / 128), 256, GSMEM_BYTES>>>(xh, xl, wqh, wql, xq, SEQLEN, QSTRIDE, DIM);
    gemm_mma<<<dim3(KSTRIDE / 128, SEQLEN / 128), 256, GSMEM_BYTES>>>(xh, xl, wkh, wkl, xk, SEQLEN, KSTRIDE, DIM);
    gemm_mma<<<dim3(KSTRIDE / 128, SEQLEN / 128), 256, GSMEM_BYTES>>>(xh, xl, wvh, wvl, xv, SEQLEN, KSTRIDE, DIM);

    // RoPE + cache
    rope_q_kernel<<<(SEQLEN * NHEADS * 64) / 256, 256>>>(xq, cf, sf);
    rope_k_cache_kernel<<<(SEQLEN * NKV * 64) / 256, 256>>>(xk, xv, cf, sf, out_ck, out_cv);
    cache_tail_kernel<<<((WINDOW - SEQLEN) * KSTRIDE) / 256, 256>>>(cki, cvi, out_ck, out_cv);

    // Attention (SIMT fp32 for now)
    flash_attn_kernel<<<dim3(SEQLEN / 64, NHEADS), 256, FLASH_SMEM_BYTES>>>(xq, xk, xv, ao);

    // Output projection on HMMA
    {
        int n = SEQLEN * QSTRIDE / 4;
        split_kernel<<<(n + 255) / 256, 256>>>(ao, aoh, aol, n);
    }
    gemm_mma<<<dim3(DIM / 128, SEQLEN / 128), 256, GSMEM_BYTES>>>(aoh, aol, woh, wol, out, SEQLEN, DIM, DIM);
}

// round 6
// speedup vs baseline: 3.3425x; 2.2226x over previous
#include <cuda_runtime.h>
#include <cuda_bf16.h>
#include <cstdint>
#include <math.h>

#define SEQLEN   2048
#define DIM      4096
#define NHEADS   32
#define NKV      8
#define HD       128
#define WINDOW   4096
#define QSTRIDE  (NHEADS * HD)   // 4096
#define KSTRIDE  (NKV * HD)      // 1024
#define ATT_SCALE 0.08838834764831843f  // 128^-0.5

// ==================== scratch (device globals; no allocs allowed) ==========
__device__ float g_xq[(size_t)SEQLEN * QSTRIDE];
__device__ float g_xk[(size_t)SEQLEN * KSTRIDE];
__device__ float g_xv[(size_t)SEQLEN * KSTRIDE];

__device__ __nv_bfloat16 g_xh [(size_t)SEQLEN * DIM];
__device__ __nv_bfloat16 g_xl [(size_t)SEQLEN * DIM];
__device__ __nv_bfloat16 g_wqh[(size_t)QSTRIDE * DIM];
__device__ __nv_bfloat16 g_wql[(size_t)QSTRIDE * DIM];
__device__ __nv_bfloat16 g_wkh[(size_t)KSTRIDE * DIM];
__device__ __nv_bfloat16 g_wkl[(size_t)KSTRIDE * DIM];
__device__ __nv_bfloat16 g_wvh[(size_t)KSTRIDE * DIM];
__device__ __nv_bfloat16 g_wvl[(size_t)KSTRIDE * DIM];
__device__ __nv_bfloat16 g_woh[(size_t)DIM * QSTRIDE];
__device__ __nv_bfloat16 g_wol[(size_t)DIM * QSTRIDE];
__device__ __nv_bfloat16 g_aoh[(size_t)SEQLEN * QSTRIDE];
__device__ __nv_bfloat16 g_aol[(size_t)SEQLEN * QSTRIDE];

// bf16 hi/lo attention operands
__device__ __nv_bfloat16 g_qh[(size_t)SEQLEN * QSTRIDE];
__device__ __nv_bfloat16 g_ql[(size_t)SEQLEN * QSTRIDE];
__device__ __nv_bfloat16 g_kh[(size_t)SEQLEN * KSTRIDE];
__device__ __nv_bfloat16 g_kl[(size_t)SEQLEN * KSTRIDE];
__device__ __nv_bfloat16 g_vh[(size_t)SEQLEN * KSTRIDE];
__device__ __nv_bfloat16 g_vl[(size_t)SEQLEN * KSTRIDE];

// ==================== helpers ===============================================
__device__ __forceinline__ void mma16816(float* c, const uint32_t* a, const uint32_t* b) {
    asm volatile(
        "mma.sync.aligned.m16n8k16.row.col.f32.bf16.bf16.f32 "
        "{%0,%1,%2,%3}, {%4,%5,%6,%7}, {%8,%9}, {%0,%1,%2,%3};"
        : "+f"(c[0]), "+f"(c[1]), "+f"(c[2]), "+f"(c[3])
        : "r"(a[0]), "r"(a[1]), "r"(a[2]), "r"(a[3]), "r"(b[0]), "r"(b[1]));
}
__device__ __forceinline__ void cp_async16(void* smem_dst, const void* gmem_src) {
    uint32_t sa;
    asm("{ .reg .u64 t; cvta.to.shared.u64 t, %1; cvt.u32.u64 %0, t; }"
        : "=r"(sa) : "l"(smem_dst));
    asm volatile("cp.async.cg.shared.global [%0], [%1], 16;" :: "r"(sa), "l"(gmem_src));
}
#define CP_COMMIT() asm volatile("cp.async.commit_group;" ::: "memory")
__device__ __forceinline__ void ldsm_x4_t(uint32_t* r, uint32_t addr) {
    asm volatile("ldmatrix.sync.aligned.m8n8.x4.trans.shared.b16 {%0,%1,%2,%3}, [%4];"
        : "=r"(r[0]), "=r"(r[1]), "=r"(r[2]), "=r"(r[3]) : "r"(addr));
}
__device__ __forceinline__ uint32_t smem_u32(const void* p) {
    uint32_t a;
    asm("{ .reg .u64 t; cvta.to.shared.u64 t, %1; cvt.u32.u64 %0, t; }"
        : "=r"(a) : "l"(p));
    return a;
}
__device__ __forceinline__ uint32_t pack2(float a, float b) {
    __nv_bfloat162 t = __floats2bfloat162_rn(a, b);
    return *(uint32_t*)&t;
}

// ==================== fp32 -> bf16 hi/lo split ==============================
__global__ void split_kernel(const float* __restrict__ src,
                             __nv_bfloat16* __restrict__ hi,
                             __nv_bfloat16* __restrict__ lo, int n4)
{
    int i = blockIdx.x * blockDim.x + threadIdx.x;
    if (i >= n4) return;
    float4 v = ((const float4*)src)[i];
    __nv_bfloat16 h0 = __float2bfloat16_rn(v.x);
    __nv_bfloat16 h1 = __float2bfloat16_rn(v.y);
    __nv_bfloat16 h2 = __float2bfloat16_rn(v.z);
    __nv_bfloat16 h3 = __float2bfloat16_rn(v.w);
    __nv_bfloat16 l0 = __float2bfloat16_rn(v.x - __bfloat162float(h0));
    __nv_bfloat16 l1 = __float2bfloat16_rn(v.y - __bfloat162float(h1));
    __nv_bfloat16 l2 = __float2bfloat16_rn(v.z - __bfloat162float(h2));
    __nv_bfloat16 l3 = __float2bfloat16_rn(v.w - __bfloat162float(h3));
    __nv_bfloat162* H = (__nv_bfloat162*)hi;
    __nv_bfloat162* L = (__nv_bfloat162*)lo;
    H[2 * i]     = __nv_bfloat162(h0, h1);
    H[2 * i + 1] = __nv_bfloat162(h2, h3);
    L[2 * i]     = __nv_bfloat162(l0, l1);
    L[2 * i + 1] = __nv_bfloat162(l2, l3);
}

// ==================== HMMA bf16x3 GEMM (unchanged, known-good) ==============
#define GPAD     40
#define SUBT_B   (128 * GPAD * 2)
#define STAGE_B  (4 * SUBT_B)
#define GSMEM_BYTES (2 * STAGE_B)

__global__ __launch_bounds__(256, 1) void gemm_mma(
    const __nv_bfloat16* __restrict__ Ah, const __nv_bfloat16* __restrict__ Al,
    const __nv_bfloat16* __restrict__ Bh, const __nv_bfloat16* __restrict__ Bl,
    float* __restrict__ C, int M, int N, int K)
{
    extern __shared__ char sm[];
    const int tid  = threadIdx.x;
    const int wid  = tid >> 5;
    const int lane = tid & 31;
    const int g    = lane >> 2;
    const int tg   = lane & 3;
    const int wm   = wid & 1;
    const int wn   = wid >> 1;
    const int bm   = blockIdx.y << 7;
    const int bn   = blockIdx.x << 7;

    const __nv_bfloat16* gsrc[4] = { Ah, Al, Bh, Bl };
    const int row0[4] = { bm, bm, bn, bn };

    auto load_stage = [&](int s, int k0) {
        char* base = sm + s * STAGE_B;
#pragma unroll
        for (int t = 0; t < 8; t++) {
            int id  = tid + (t << 8);
            int sub = id >> 9;
            int idx = id & 511;
            int r   = idx >> 2;
            int c   = idx & 3;
            char* dst = base + sub * SUBT_B + r * (GPAD * 2) + c * 16;
            const __nv_bfloat16* src =
                gsrc[sub] + (size_t)(row0[sub] + r) * K + k0 + c * 8;
            cp_async16(dst, src);
        }
        CP_COMMIT();
    };

    float acc[4][4][4];
#pragma unroll
    for (int m = 0; m < 4; m++)
#pragma unroll
        for (int n = 0; n < 4; n++)
#pragma unroll
            for (int k = 0; k < 4; k++) acc[m][n][k] = 0.f;

    const int NIT = K >> 5;
    load_stage(0, 0);

    for (int it = 0; it < NIT; it++) {
        asm volatile("cp.async.wait_group 0;" ::: "memory");
        __syncthreads();
        if (it + 1 < NIT) load_stage((it + 1) & 1, (it + 1) << 5);

        const char* base = sm + (it & 1) * STAGE_B;
        const __nv_bfloat16* Ahs = (const __nv_bfloat16*)(base + 0 * SUBT_B);
        const __nv_bfloat16* Als = (const __nv_bfloat16*)(base + 1 * SUBT_B);
        const __nv_bfloat16* Bhs = (const __nv_bfloat16*)(base + 2 * SUBT_B);
        const __nv_bfloat16* Bls = (const __nv_bfloat16*)(base + 3 * SUBT_B);

#pragma unroll
        for (int ks = 0; ks < 32; ks += 16) {
            uint32_t bh[4][2], bl[4][2];
#pragma unroll
            for (int n = 0; n < 4; n++) {
                int nr = wn * 32 + n * 8 + g;
                bh[n][0] = *(const uint32_t*)&Bhs[nr * GPAD + ks + 2 * tg];
                bh[n][1] = *(const uint32_t*)&Bhs[nr * GPAD + ks + 8 + 2 * tg];
                bl[n][0] = *(const uint32_t*)&Bls[nr * GPAD + ks + 2 * tg];
                bl[n][1] = *(const uint32_t*)&Bls[nr * GPAD + ks + 8 + 2 * tg];
            }
#pragma unroll
            for (int m = 0; m < 4; m++) {
                int mr = wm * 64 + m * 16;
                uint32_t ah[4], al[4];
                ah[0] = *(const uint32_t*)&Ahs[(mr + g)     * GPAD + ks + 2 * tg];
                ah[1] = *(const uint32_t*)&Ahs[(mr + 8 + g) * GPAD + ks + 2 * tg];
                ah[2] = *(const uint32_t*)&Ahs[(mr + g)     * GPAD + ks + 8 + 2 * tg];
                ah[3] = *(const uint32_t*)&Ahs[(mr + 8 + g) * GPAD + ks + 8 + 2 * tg];
                al[0] = *(const uint32_t*)&Als[(mr + g)     * GPAD + ks + 2 * tg];
                al[1] = *(const uint32_t*)&Als[(mr + 8 + g) * GPAD + ks + 2 * tg];
                al[2] = *(const uint32_t*)&Als[(mr + g)     * GPAD + ks + 8 + 2 * tg];
                al[3] = *(const uint32_t*)&Als[(mr + 8 + g) * GPAD + ks + 8 + 2 * tg];
#pragma unroll
                for (int n = 0; n < 4; n++) {
                    mma16816(acc[m][n], ah, bh[n]);
                    mma16816(acc[m][n], ah, bl[n]);
                    mma16816(acc[m][n], al, bh[n]);
                }
            }
        }
        __syncthreads();
    }

#pragma unroll
    for (int m = 0; m < 4; m++) {
        int r0 = bm + wm * 64 + m * 16 + g;
#pragma unroll
        for (int n = 0; n < 4; n++) {
            int col = bn + wn * 32 + n * 8 + 2 * tg;
            *(float2*)&C[(size_t)r0 * N + col] =
                make_float2(acc[m][n][0], acc[m][n][1]);
            *(float2*)&C[(size_t)(r0 + 8) * N + col] =
                make_float2(acc[m][n][2], acc[m][n][3]);
        }
    }
}

// ==================== RoPE + hi/lo split kernels ============================
__global__ void rope_q_split(const float* __restrict__ xq,
                             const float* __restrict__ cf,
                             const float* __restrict__ sf,
                             __nv_bfloat16* __restrict__ Qh,
                             __nv_bfloat16* __restrict__ Ql)
{
    int idx = blockIdx.x * blockDim.x + threadIdx.x;   // SEQLEN*32*64
    if (idx >= SEQLEN * NHEADS * 64) return;
    int d = idx & 63;
    int h = (idx >> 6) & (NHEADS - 1);
    int p = idx >> 11;
    float c = cf[p * 64 + d];
    float s = sf[p * 64 + d];
    size_t off = ((size_t)p * NHEADS + h) * HD + 2 * d;
    float e = xq[off], o = xq[off + 1];
    float r1 = (e * c - o * s) * ATT_SCALE;
    float r2 = (e * s + o * c) * ATT_SCALE;
    __nv_bfloat16 h1 = __float2bfloat16_rn(r1);
    __nv_bfloat16 h2 = __float2bfloat16_rn(r2);
    ((__nv_bfloat162*)Qh)[off >> 1] = __nv_bfloat162(h1, h2);
    ((__nv_bfloat162*)Ql)[off >> 1] = __nv_bfloat162(
        __float2bfloat16_rn(r1 - __bfloat162float(h1)),
        __float2bfloat16_rn(r2 - __bfloat162float(h2)));
}

__global__ void rope_kv_split_cache(const float* __restrict__ xk,
                                    const float* __restrict__ xv,
                                    const float* __restrict__ cf,
                                    const float* __restrict__ sf,
                                    float* __restrict__ ck, float* __restrict__ cv,
                                    __nv_bfloat16* __restrict__ Kh,
                                    __nv_bfloat16* __restrict__ Kl,
                                    __nv_bfloat16* __restrict__ Vh,
                                    __nv_bfloat16* __restrict__ Vl)
{
    int idx = blockIdx.x * blockDim.x + threadIdx.x;   // SEQLEN*8*64
    if (idx >= SEQLEN * NKV * 64) return;
    int d = idx & 63;
    int h = (idx >> 6) & (NKV - 1);
    int p = idx >> 9;
    float c = cf[p * 64 + d];
    float s = sf[p * 64 + d];
    size_t off = ((size_t)p * NKV + h) * HD + 2 * d;
    float e = xk[off], o = xk[off + 1];
    float r1 = e * c - o * s;
    float r2 = e * s + o * c;
    ck[off] = r1; ck[off + 1] = r2;
    __nv_bfloat16 kh1 = __float2bfloat16_rn(r1);
    __nv_bfloat16 kh2 = __float2bfloat16_rn(r2);
    ((__nv_bfloat162*)Kh)[off >> 1] = __nv_bfloat162(kh1, kh2);
    ((__nv_bfloat162*)Kl)[off >> 1] = __nv_bfloat162(
        __float2bfloat16_rn(r1 - __bfloat162float(kh1)),
        __float2bfloat16_rn(r2 - __bfloat162float(kh2)));
    float v1 = xv[off], v2 = xv[off + 1];
    cv[off] = v1; cv[off + 1] = v2;
    __nv_bfloat16 vh1 = __float2bfloat16_rn(v1);
    __nv_bfloat16 vh2 = __float2bfloat16_rn(v2);
    ((__nv_bfloat162*)Vh)[off >> 1] = __nv_bfloat162(vh1, vh2);
    ((__nv_bfloat162*)Vl)[off >> 1] = __nv_bfloat162(
        __float2bfloat16_rn(v1 - __bfloat162float(vh1)),
        __float2bfloat16_rn(v2 - __bfloat162float(vh2)));
}

__global__ void cache_tail_kernel(const float* __restrict__ cki,
                                  const float* __restrict__ cvi,
                                  float* __restrict__ cko,
                                  float* __restrict__ cvo)
{
    int idx = blockIdx.x * blockDim.x + threadIdx.x;
    if (idx >= (WINDOW - SEQLEN) * KSTRIDE) return;
    size_t off = (size_t)SEQLEN * KSTRIDE + idx;
    cko[off] = cki[off];
    cvo[off] = cvi[off];
}

// ==================== HMMA flash attention (bf16x3, causal) =================
// CTA: 128 q-rows x 1 head; 8 warps x 16 rows; kv tiles of 64, 2-stage cp.async
#define SPAD      136
#define Q_ELEMS   (128 * SPAD)
#define KV_ELEMS  (64 * SPAD)
#define ATT_SMEM  ((2 * Q_ELEMS + 8 * KV_ELEMS) * 2)   // 208896 bytes

__global__ __launch_bounds__(256, 1) void flash_mma(
    const __nv_bfloat16* __restrict__ Qhg, const __nv_bfloat16* __restrict__ Qlg,
    const __nv_bfloat16* __restrict__ Khg, const __nv_bfloat16* __restrict__ Klg,
    const __nv_bfloat16* __restrict__ Vhg, const __nv_bfloat16* __restrict__ Vlg,
    __nv_bfloat16* __restrict__ Ohg, __nv_bfloat16* __restrict__ Olg)
{
    extern __shared__ __nv_bfloat16 sb[];
    const int tid  = threadIdx.x;
    const int wid  = tid >> 5;
    const int lane = tid & 31;
    const int g    = lane >> 2;
    const int tg   = lane & 3;
    const int qb   = (int)(gridDim.x - 1 - blockIdx.x);   // heavy blocks first
    const int h    = blockIdx.y;
    const int kvh  = h >> 2;
    const int q0   = qb << 7;
    const int mr   = wid << 4;

    __nv_bfloat16* Qhs = sb;
    __nv_bfloat16* Qls = sb + Q_ELEMS;
    __nv_bfloat16* KVs = sb + 2 * Q_ELEMS;
    const uint32_t sbase = smem_u32(sb);

    // ---- stage Q (hi + lo) ----
    {
        const __nv_bfloat16* gq[2] = { Qhg, Qlg };
#pragma unroll
        for (int i = 0; i < 16; i++) {
            int id  = tid + (i << 8);
            int tsr = id >> 11, idx = id & 2047;
            int r = idx >> 4, c = idx & 15;
            cp_async16(sb + tsr * Q_ELEMS + r * SPAD + c * 8,
                       gq[tsr] + (size_t)(q0 + r) * QSTRIDE + h * HD + c * 8);
        }
        CP_COMMIT();
    }

    const int NT = 2 * qb + 2;
    const __nv_bfloat16* gkv[4] = { Khg, Klg, Vhg, Vlg };
    auto load_kv = [&](int t, int st) {
        __nv_bfloat16* base = KVs + st * 4 * KV_ELEMS;
#pragma unroll
        for (int i = 0; i < 16; i++) {
            int id  = tid + (i << 8);
            int sub = id >> 10, idx = id & 1023;
            int r = idx >> 4, c = idx & 15;
            cp_async16(base + sub * KV_ELEMS + r * SPAD + c * 8,
                       gkv[sub] + (size_t)(t * 64 + r) * KSTRIDE + kvh * HD + c * 8);
        }
        CP_COMMIT();
    };
    load_kv(0, 0);

    float m0 = -1e30f, m1 = -1e30f, l0 = 0.f, l1 = 0.f;
    float o[16][4];
#pragma unroll
    for (int n = 0; n < 16; n++)
#pragma unroll
        for (int c = 0; c < 4; c++) o[n][c] = 0.f;

    for (int t = 0; t < NT; t++) {
        if (t + 1 < NT) {
            load_kv(t + 1, (t + 1) & 1);
            asm volatile("cp.async.wait_group 1;" ::: "memory");
        } else {
            asm volatile("cp.async.wait_group 0;" ::: "memory");
        }
        __syncthreads();

        if (t * 64 <= q0 + mr + 15) {   // warp has unmasked rows in this tile
            const __nv_bfloat16* Khs = KVs + (t & 1) * 4 * KV_ELEMS;
            const __nv_bfloat16* Kls = Khs + KV_ELEMS;
            const uint32_t vh_base = sbase +
                (uint32_t)(2 * Q_ELEMS + (t & 1) * 4 * KV_ELEMS + 2 * KV_ELEMS) * 2;
            const uint32_t vl_base = vh_base + KV_ELEMS * 2;

            // ---- S = Q K^T (bf16x3) ----
            float sc[8][4];
#pragma unroll
            for (int n = 0; n < 8; n++)
#pragma unroll
                for (int c = 0; c < 4; c++) sc[n][c] = 0.f;

#pragma unroll
            for (int k = 0; k < 8; k++) {
                int ks = k << 4;
                uint32_t qh[4], ql[4];
                qh[0] = *(const uint32_t*)&Qhs[(mr + g)     * SPAD + ks + 2 * tg];
                qh[1] = *(const uint32_t*)&Qhs[(mr + 8 + g) * SPAD + ks + 2 * tg];
                qh[2] = *(const uint32_t*)&Qhs[(mr + g)     * SPAD + ks + 8 + 2 * tg];
                qh[3] = *(const uint32_t*)&Qhs[(mr + 8 + g) * SPAD + ks + 8 + 2 * tg];
                ql[0] = *(const uint32_t*)&Qls[(mr + g)     * SPAD + ks + 2 * tg];
                ql[1] = *(const uint32_t*)&Qls[(mr + 8 + g) * SPAD + ks + 2 * tg];
                ql[2] = *(const uint32_t*)&Qls[(mr + g)     * SPAD + ks + 8 + 2 * tg];
                ql[3] = *(const uint32_t*)&Qls[(mr + 8 + g) * SPAD + ks + 8 + 2 * tg];
#pragma unroll
                for (int n = 0; n < 8; n++) {
                    uint32_t kh[2], kl[2];
                    kh[0] = *(const uint32_t*)&Khs[(8 * n + g) * SPAD + ks + 2 * tg];
                    kh[1] = *(const uint32_t*)&Khs[(8 * n + g) * SPAD + ks + 8 + 2 * tg];
                    kl[0] = *(const uint32_t*)&Kls[(8 * n + g) * SPAD + ks + 2 * tg];
                    kl[1] = *(const uint32_t*)&Kls[(8 * n + g) * SPAD + ks + 8 + 2 * tg];
                    mma16816(sc[n], qh, kh);
                    mma16816(sc[n], qh, kl);
                    mma16816(sc[n], ql, kh);
                }
            }

            // ---- causal mask (only near diagonal) ----
            const int qi0 = q0 + mr + g, qi1 = qi0 + 8;
            if (t * 64 + 63 > q0 + mr) {
#pragma unroll
                for (int n = 0; n < 8; n++) {
                    int kj = t * 64 + 8 * n + 2 * tg;
                    if (kj     > qi0) sc[n][0] = -1e30f;
                    if (kj + 1 > qi0) sc[n][1] = -1e30f;
                    if (kj     > qi1) sc[n][2] = -1e30f;
                    if (kj + 1 > qi1) sc[n][3] = -1e30f;
                }
            }

            // ---- online softmax (per-row; quad shuffle) ----
            float mt0 = -1e30f, mt1 = -1e30f;
#pragma unroll
            for (int n = 0; n < 8; n++) {
                mt0 = fmaxf(mt0, fmaxf(sc[n][0], sc[n][1]));
                mt1 = fmaxf(mt1, fmaxf(sc[n][2], sc[n][3]));
            }
            mt0 = fmaxf(mt0, __shfl_xor_sync(0xffffffffu, mt0, 1));
            mt0 = fmaxf(mt0, __shfl_xor_sync(0xffffffffu, mt0, 2));
            mt1 = fmaxf(mt1, __shfl_xor_sync(0xffffffffu, mt1, 1));
            mt1 = fmaxf(mt1, __shfl_xor_sync(0xffffffffu, mt1, 2));
            float m0n = fmaxf(m0, mt0), m1n = fmaxf(m1, mt1);
            float c0 = __expf(m0 - m0n), c1 = __expf(m1 - m1n);
            float rs0 = 0.f, rs1 = 0.f;
#pragma unroll
            for (int n = 0; n < 8; n++) {
                sc[n][0] = __expf(sc[n][0] - m0n);
                sc[n][1] = __expf(sc[n][1] - m0n);
                sc[n][2] = __expf(sc[n][2] - m1n);
                sc[n][3] = __expf(sc[n][3] - m1n);
                rs0 += sc[n][0] + sc[n][1];
                rs1 += sc[n][2] + sc[n][3];
            }
            rs0 += __shfl_xor_sync(0xffffffffu, rs0, 1);
            rs0 += __shfl_xor_sync(0xffffffffu, rs0, 2);
            rs1 += __shfl_xor_sync(0xffffffffu, rs1, 1);
            rs1 += __shfl_xor_sync(0xffffffffu, rs1, 2);
            l0 = l0 * c0 + rs0;
            l1 = l1 * c1 + rs1;
            m0 = m0n; m1 = m1n;
#pragma unroll
            for (int n = 0; n < 16; n++) {
                o[n][0] *= c0; o[n][1] *= c0; o[n][2] *= c1; o[n][3] *= c1;
            }

            // ---- P -> bf16 hi/lo A-fragments (in registers) ----
            uint32_t ph[4][4], pl[4][4];
#pragma unroll
            for (int j = 0; j < 4; j++) {
                const float* A = sc[2 * j];
                const float* B = sc[2 * j + 1];
                float ah0 = __bfloat162float(__float2bfloat16_rn(A[0]));
                float ah1 = __bfloat162float(__float2bfloat16_rn(A[1]));
                float ah2 = __bfloat162float(__float2bfloat16_rn(A[2]));
                float ah3 = __bfloat162float(__float2bfloat16_rn(A[3]));
                float bh0 = __bfloat162float(__float2bfloat16_rn(B[0]));
                float bh1 = __bfloat162float(__float2bfloat16_rn(B[1]));
                float bh2 = __bfloat162float(__float2bfloat16_rn(B[2]));
                float bh3 = __bfloat162float(__float2bfloat16_rn(B[3]));
                ph[j][0] = pack2(ah0, ah1);
                ph[j][1] = pack2(ah2, ah3);
                ph[j][2] = pack2(bh0, bh1);
                ph[j][3] = pack2(bh2, bh3);
                pl[j][0] = pack2(A[0] - ah0, A[1] - ah1);
                pl[j][1] = pack2(A[2] - ah2, A[3] - ah3);
                pl[j][2] = pack2(B[0] - bh0, B[1] - bh1);
                pl[j][3] = pack2(B[2] - bh2, B[3] - bh3);
            }

            // ---- O += P V (bf16x3), V frags via ldmatrix.trans ----
            const uint32_t va = (uint32_t)(((lane & 15) * SPAD + ((lane >> 4) << 3)) * 2);
#pragma unroll
            for (int j = 0; j < 4; j++) {
                const uint32_t kvoff = va + (uint32_t)(16 * j * SPAD * 2);
#pragma unroll
                for (int u = 0; u < 8; u++) {
                    uint32_t vh[4], vl[4];
                    ldsm_x4_t(vh, vh_base + kvoff + u * 32);
                    ldsm_x4_t(vl, vl_base + kvoff + u * 32);
                    mma16816(o[2 * u],     ph[j], &vh[0]);
                    mma16816(o[2 * u],     ph[j], &vl[0]);
                    mma16816(o[2 * u],     pl[j], &vh[0]);
                    mma16816(o[2 * u + 1], ph[j], &vh[2]);
                    mma16816(o[2 * u + 1], ph[j], &vl[2]);
                    mma16816(o[2 * u + 1], pl[j], &vh[2]);
                }
            }
        }
        __syncthreads();
    }

    // ---- epilogue: normalize, split hi/lo, store bf16 ----
    const float inv0 = 1.f / l0, inv1 = 1.f / l1;
    const int row0 = q0 + mr + g, row1 = row0 + 8;
#pragma unroll
    for (int n = 0; n < 16; n++) {
        int col = h * HD + 8 * n + 2 * tg;
        float f00 = o[n][0] * inv0, f01 = o[n][1] * inv0;
        float f10 = o[n][2] * inv1, f11 = o[n][3] * inv1;
        float h00 = __bfloat162float(__float2bfloat16_rn(f00));
        float h01 = __bfloat162float(__float2bfloat16_rn(f01));
        float h10 = __bfloat162float(__float2bfloat16_rn(f10));
        float h11 = __bfloat162float(__float2bfloat16_rn(f11));
        *(uint32_t*)&Ohg[(size_t)row0 * QSTRIDE + col] = pack2(h00, h01);
        *(uint32_t*)&Olg[(size_t)row0 * QSTRIDE + col] = pack2(f00 - h00, f01 - h01);
        *(uint32_t*)&Ohg[(size_t)row1 * QSTRIDE + col] = pack2(h10, h11);
        *(uint32_t*)&Olg[(size_t)row1 * QSTRIDE + col] = pack2(f10 - h10, f11 - h11);
    }
}

// ==================== launch ================================================
extern "C" void kernel_launch(void* const* d_in, const int* in_sizes, int n_in,
                              void* d_out, int out_size)
{
    (void)in_sizes; (void)n_in; (void)out_size;
    const float* x   = (const float*)d_in[0];
    const float* cf  = (const float*)d_in[1];
    const float* sf  = (const float*)d_in[2];
    const float* cki = (const float*)d_in[5];
    const float* cvi = (const float*)d_in[6];
    const float* wq  = (const float*)d_in[7];
    const float* wk  = (const float*)d_in[8];
    const float* wv  = (const float*)d_in[9];
    const float* wo  = (const float*)d_in[10];

    float* out    = (float*)d_out;
    float* out_ck = out + (size_t)SEQLEN * DIM;
    float* out_cv = out_ck + (size_t)WINDOW * KSTRIDE;

    float *xq, *xk, *xv;
    cudaGetSymbolAddress((void**)&xq, g_xq);
    cudaGetSymbolAddress((void**)&xk, g_xk);
    cudaGetSymbolAddress((void**)&xv, g_xv);
    __nv_bfloat16 *xh, *xl, *wqh, *wql, *wkh, *wkl, *wvh, *wvl, *woh, *wol, *aoh, *aol;
    __nv_bfloat16 *qh, *ql, *kh, *kl, *vh, *vl;
    cudaGetSymbolAddress((void**)&xh,  g_xh);
    cudaGetSymbolAddress((void**)&xl,  g_xl);
    cudaGetSymbolAddress((void**)&wqh, g_wqh);
    cudaGetSymbolAddress((void**)&wql, g_wql);
    cudaGetSymbolAddress((void**)&wkh, g_wkh);
    cudaGetSymbolAddress((void**)&wkl, g_wkl);
    cudaGetSymbolAddress((void**)&wvh, g_wvh);
    cudaGetSymbolAddress((void**)&wvl, g_wvl);
    cudaGetSymbolAddress((void**)&woh, g_woh);
    cudaGetSymbolAddress((void**)&wol, g_wol);
    cudaGetSymbolAddress((void**)&aoh, g_aoh);
    cudaGetSymbolAddress((void**)&aol, g_aol);
    cudaGetSymbolAddress((void**)&qh,  g_qh);
    cudaGetSymbolAddress((void**)&ql,  g_ql);
    cudaGetSymbolAddress((void**)&kh,  g_kh);
    cudaGetSymbolAddress((void**)&kl,  g_kl);
    cudaGetSymbolAddress((void**)&vh,  g_vh);
    cudaGetSymbolAddress((void**)&vl,  g_vl);

    cudaFuncSetAttribute(gemm_mma,
                         cudaFuncAttributeMaxDynamicSharedMemorySize, GSMEM_BYTES);
    cudaFuncSetAttribute(flash_mma,
                         cudaFuncAttributeMaxDynamicSharedMemorySize, ATT_SMEM);

    // splits
    {
        int n;
        n = SEQLEN * DIM / 4;    split_kernel<<<(n + 255) / 256, 256>>>(x,  xh,  xl,  n);
        n = QSTRIDE * DIM / 4;   split_kernel<<<(n + 255) / 256, 256>>>(wq, wqh, wql, n);
        n = KSTRIDE * DIM / 4;   split_kernel<<<(n + 255) / 256, 256>>>(wk, wkh, wkl, n);
        n = KSTRIDE * DIM / 4;   split_kernel<<<(n + 255) / 256, 256>>>(wv, wvh, wvl, n);
        n = DIM * QSTRIDE / 4;   split_kernel<<<(n + 255) / 256, 256>>>(wo, woh, wol, n);
    }

    // QKV projections
    gemm_mma<<<dim3(QSTRIDE / 128, SEQLEN / 128), 256, GSMEM_BYTES>>>(xh, xl, wqh, wql, xq, SEQLEN, QSTRIDE, DIM);
    gemm_mma<<<dim3(KSTRIDE / 128, SEQLEN / 128), 256, GSMEM_BYTES>>>(xh, xl, wkh, wkl, xk, SEQLEN, KSTRIDE, DIM);
    gemm_mma<<<dim3(KSTRIDE / 128, SEQLEN / 128), 256, GSMEM_BYTES>>>(xh, xl, wvh, wvl, xv, SEQLEN, KSTRIDE, DIM);

    // RoPE + splits + cache
    rope_q_split<<<(SEQLEN * NHEADS * 64) / 256, 256>>>(xq, cf, sf, qh, ql);
    rope_kv_split_cache<<<(SEQLEN * NKV * 64) / 256, 256>>>(xk, xv, cf, sf,
                                                            out_ck, out_cv, kh, kl, vh, vl);
    cache_tail_kernel<<<((WINDOW - SEQLEN) * KSTRIDE) / 256, 256>>>(cki, cvi, out_ck, out_cv);

    // HMMA flash attention -> aoh/aol (bf16 hi/lo directly)
    flash_mma<<<dim3(SEQLEN / 128, NHEADS), 256, ATT_SMEM>>>(qh, ql, kh, kl, vh, vl, aoh, aol);

    // Output projection
    gemm_mma<<<dim3(DIM / 128, SEQLEN / 128), 256, GSMEM_BYTES>>>(aoh, aol, woh, wol, out, SEQLEN, DIM, DIM);
}